// round 15
// baseline (speedup 1.0000x reference)
#include <cuda_runtime.h>
#include <cuda_fp16.h>
#include <math_constants.h>
#include <stdint.h>

// Problem dims
#define B_   4
#define T_   1024
#define H_   12
#define C_   4096
#define DK_  64
#define DV_  64
#define N_   (B_*T_)      // 4096
#define DIM_ (H_*DK_)     // 768

// GEMM config: single-phase fp16 (K=64), certification window handles error.
#define TM   128          // rows per CTA
#define TCC  64           // codes per iteration
#define NCT  (C_/TCC)     // 64
#define SA   144          // smem row stride bytes (128 data + 16 pad)
#define B_TILE_BYTES (TCC*SA)     // 9216
#define W_SEL 5e-4f       // ambiguity window (~20 sigma of fp16-GEMM error)

// smem offsets: B triple-buffered (distance-2 pipeline)
#define OFF_A   0                 // 128 * 144 = 18432
#define OFF_B   18432             // 3 buffers of 9216 = 27648
#define OFF_E2  46080             // float e2s[3][64] = 768
#define SMEM_SZ 46848

// Device scratch
__device__ __align__(1024) __half g_Bh[(size_t)H_*C_*DK_];
__device__ float g_e2[H_*C_];
__device__ int   g_idx[H_*N_];
__device__ int   g_listB[H_*N_];
__device__ int   g_cntB;

// ---------------- helpers ----------------
__device__ __forceinline__ uint32_t smem_u32(const void* p) {
    uint32_t a;
    asm("{ .reg .u64 t; cvta.to.shared.u64 t, %1; cvt.u32.u64 %0, t; }" : "=r"(a) : "l"(p));
    return a;
}
__device__ __forceinline__ void cpa16(uint32_t dst, const void* src) {
    asm volatile("cp.async.cg.shared.global [%0], [%1], 16;" :: "r"(dst), "l"(src));
}
__device__ __forceinline__ void cpa_commit() { asm volatile("cp.async.commit_group;" ::: "memory"); }
__device__ __forceinline__ void cpa_wait0()  { asm volatile("cp.async.wait_group 0;" ::: "memory"); }
__device__ __forceinline__ void cpa_wait1()  { asm volatile("cp.async.wait_group 1;" ::: "memory"); }

__device__ __forceinline__ void ldsm4(uint32_t* r, uint32_t addr) {
    asm volatile("ldmatrix.sync.aligned.m8n8.x4.shared.b16 {%0,%1,%2,%3}, [%4];"
                 : "=r"(r[0]), "=r"(r[1]), "=r"(r[2]), "=r"(r[3]) : "r"(addr));
}
__device__ __forceinline__ void mma16816(float* d, const uint32_t* a, const uint32_t* b) {
    asm volatile("mma.sync.aligned.m16n8k16.row.col.f32.f16.f16.f32 "
                 "{%0,%1,%2,%3}, {%4,%5,%6,%7}, {%8,%9}, {%0,%1,%2,%3};"
                 : "+f"(d[0]), "+f"(d[1]), "+f"(d[2]), "+f"(d[3])
                 : "r"(a[0]), "r"(a[1]), "r"(a[2]), "r"(a[3]), "r"(b[0]), "r"(b[1]));
}

__device__ __forceinline__ void merge3(float& m1, int& i1, float& m2, int& i2, float& m3,
                                       float bm1, int bi1, float bm2, int bi2, float bm3) {
    if (bm1 < m1 || (bm1 == m1 && bi1 < i1)) {
        float t; int ti;
        t = m1; m1 = bm1; bm1 = t;  ti = i1; i1 = bi1; bi1 = ti;
        t = m2; m2 = bm2; bm2 = t;  ti = i2; i2 = bi2; bi2 = ti;
        t = m3; m3 = bm3; bm3 = t;
    }
    if (bm1 < m2 || (bm1 == m2 && bi1 < i2)) {
        m3 = fminf(m2, bm2);
        m2 = bm1; i2 = bi1;
    } else {
        m3 = fminf(m3, bm1);
    }
}

__device__ __forceinline__ void ins3(float s, int c, float& m1, int& i1,
                                     float& m2, int& i2, float& m3) {
    if (s < m1)      { m3 = m2; m2 = m1; i2 = i1; m1 = s; i1 = c; }
    else if (s < m2) { m3 = m2; m2 = s; i2 = c; }
    else if (s < m3) { m3 = s; }
}

// ---------------------------------------------------------------------------
// Fused prep: e2 (exact sequential order) + B fp16 convert
// ---------------------------------------------------------------------------
__global__ void prep_be2_kernel(const float* __restrict__ ke) {
    __shared__ float kt[64 * 65];
    const int tid = threadIdx.x;
    const int row0 = blockIdx.x * 64;
    if (blockIdx.x == 0 && tid == 0) g_cntB = 0;

#pragma unroll 4
    for (int m = tid; m < 64 * 16; m += 256) {
        int r = m >> 4, c4 = m & 15;
        float4 v = *(const float4*)(ke + (size_t)(row0 + r) * DK_ + c4 * 4);
        kt[r * 65 + c4 * 4 + 0] = v.x;
        kt[r * 65 + c4 * 4 + 1] = v.y;
        kt[r * 65 + c4 * 4 + 2] = v.z;
        kt[r * 65 + c4 * 4 + 3] = v.w;
    }
    __syncthreads();

    if (tid < 64) {
        float s = 0.f;
#pragma unroll
        for (int d = 0; d < DK_; d++) {
            float v = kt[tid * 65 + d];
            s = __fmaf_rn(v, v, s);
        }
        g_e2[row0 + tid] = s;
    }

#pragma unroll 4
    for (int m = tid; m < 64 * 32; m += 256) {
        int r = m >> 5, dp = m & 31;
        __half2 hv = __floats2half2_rn(kt[r * 65 + dp * 2], kt[r * 65 + dp * 2 + 1]);
        *(__half2*)(g_Bh + (size_t)(row0 + r) * DK_ + dp * 2) = hv;
    }
}

// ---------------------------------------------------------------------------
// Main: fp16 HMMA GEMM (K=64) + top-3 argmin; persistent A frags;
// distance-2 triple-buffered cp.async pipeline
// grid = (32, 12); block = 128 (4 warps, each 32 rows x 64 cols)
// ---------------------------------------------------------------------------
__global__ __launch_bounds__(128, 3)
void hmma_argmin_kernel(const float* __restrict__ x,
                        const float* __restrict__ ke) {
    extern __shared__ char smem[];
    const uint32_t sb = smem_u32(smem);
    const int tid = threadIdx.x, lane = tid & 31, wid = tid >> 5;
    const int h = blockIdx.y, ntb = blockIdx.x;

    float* e2s = (float*)(smem + OFF_E2);      // [3][64]

    const __half* Bg = g_Bh + (size_t)h * C_ * DK_;
    const float* e2h = g_e2 + h * C_;

    // Prologue: tiles 0 and 1 committed as separate groups
#pragma unroll 4
    for (int m = tid; m < TCC * 8; m += 128)
        cpa16(sb + OFF_B + (m >> 3) * SA + (m & 7) * 16, Bg + m * 8);
    if (tid < 16) cpa16(sb + OFF_E2 + tid * 16, e2h + tid * 4);
    cpa_commit();
#pragma unroll 4
    for (int m = tid; m < TCC * 8; m += 128)
        cpa16(sb + OFF_B + B_TILE_BYTES + (m >> 3) * SA + (m & 7) * 16,
              Bg + TCC * DK_ + m * 8);
    if (tid < 16) cpa16(sb + OFF_E2 + 256 + tid * 16, e2h + TCC + tid * 4);
    cpa_commit();

    // A tile converted in-kernel to fp16: 128 rows x 128 B
    {
        const float* xb = x + (size_t)(ntb * TM) * DIM_ + h * DK_;
#pragma unroll 8
        for (int m = tid; m < TM * 32; m += 128) {
            int r = m >> 5, dp = m & 31;
            float2 v = *(const float2*)(xb + (size_t)r * DIM_ + dp * 2);
            __half2 hv = __floats2half2_rn(v.x, v.y);
            *(__half2*)(smem + OFF_A + r * SA + dp * 4) = hv;
        }
    }
    __syncthreads();   // A tile visible

    // ldmatrix bases
    const uint32_t aAddr = sb + OFF_A +
        (uint32_t)((wid * 32 + (lane & 15)) * SA + (lane >> 4) * 16);
    const uint32_t bAddrBase =
        (uint32_t)(((lane & 7) + ((lane >> 4) & 1) * 8) * SA +
                   ((lane >> 3) & 1) * 16);

    // Persistent A fragments: identical across all 64 ct iterations
    uint32_t afr[4][2][4];
#pragma unroll
    for (int ks = 0; ks < 4; ks++)
#pragma unroll
        for (int mt = 0; mt < 2; mt++)
            ldsm4(afr[ks][mt], aAddr + mt * (16 * SA) + ks * 32);

    float m1[4], m2[4], m3[4]; int i1[4], i2[4];
#pragma unroll
    for (int q = 0; q < 4; q++) {
        m1[q] = CUDART_INF_F; m2[q] = CUDART_INF_F; m3[q] = CUDART_INF_F;
        i1[q] = 0; i2[q] = 0;
    }

    int bc = 0;                    // buffer of tile ct (ct % 3)
    for (int ct = 0; ct < NCT; ct++) {
        // tile ct complete: FIFO order means <=1 pending implies ct done
        if (ct + 1 < NCT) cpa_wait1(); else cpa_wait0();
        __syncthreads();           // all warps done reading buffer bp (ct-1 epi)

        // prefetch tile ct+2 into buffer (bc+2)%3 (last read at iter ct-1)
        if (ct + 2 < NCT) {
            int bp = bc + 2; if (bp >= 3) bp -= 3;
            const __half* Bt = Bg + (size_t)(ct + 2) * TCC * DK_;
            uint32_t dstb = sb + OFF_B + bp * B_TILE_BYTES;
#pragma unroll 4
            for (int m = tid; m < TCC * 8; m += 128)
                cpa16(dstb + (m >> 3) * SA + (m & 7) * 16, Bt + m * 8);
            if (tid < 16)
                cpa16(sb + OFF_E2 + bp * 256 + tid * 16,
                      e2h + (ct + 2) * TCC + tid * 4);
            cpa_commit();
        }

        float acc[2][8][4];
#pragma unroll
        for (int mt = 0; mt < 2; mt++)
#pragma unroll
            for (int nt = 0; nt < 8; nt++)
#pragma unroll
                for (int v = 0; v < 4; v++) acc[mt][nt][v] = 0.f;

        const uint32_t bAddr = sb + OFF_B + bc * B_TILE_BYTES + bAddrBase;

#pragma unroll
        for (int ks = 0; ks < 4; ks++) {
            uint32_t b[4][4];
#pragma unroll
            for (int np = 0; np < 4; np++)
                ldsm4(b[np], bAddr + np * (16 * SA) + ks * 32);
#pragma unroll
            for (int mt = 0; mt < 2; mt++)
#pragma unroll
                for (int nt = 0; nt < 8; nt++)
                    mma16816(acc[mt][nt], afr[ks][mt], &b[nt >> 1][(nt & 1) * 2]);
        }

        // epilogue: s = e2 - 2*dot; paired fminf fast path vs m3
        const float* e2c = e2s + bc * 64 + (lane & 3) * 2;
        const int cth = ct * TCC + (lane & 3) * 2;
#pragma unroll
        for (int nt = 0; nt < 8; nt++) {
            float e20 = e2c[nt * 8], e21 = e2c[nt * 8 + 1];
#pragma unroll
            for (int mt = 0; mt < 2; mt++) {
#pragma unroll
                for (int vp = 0; vp < 2; vp++) {
                    float s0 = fmaf(-2.f, acc[mt][nt][vp * 2],     e20);
                    float s1 = fmaf(-2.f, acc[mt][nt][vp * 2 + 1], e21);
                    int q = mt * 2 + vp;
                    if (fminf(s0, s1) < m3[q]) {        // rare after warmup
                        int c = cth + nt * 8;
                        ins3(s0, c,     m1[q], i1[q], m2[q], i2[q], m3[q]);
                        ins3(s1, c + 1, m1[q], i1[q], m2[q], i2[q], m3[q]);
                    }
                }
            }
        }
        bc = bc + 1; if (bc >= 3) bc = 0;
    }

    // quad reduce (lanes xor 1,2 cover disjoint columns, same rows)
#pragma unroll
    for (int q = 0; q < 4; q++) {
#pragma unroll
        for (int d = 1; d <= 2; d <<= 1) {
            float bm1 = __shfl_xor_sync(0xffffffffu, m1[q], d);
            int   bi1 = __shfl_xor_sync(0xffffffffu, i1[q], d);
            float bm2 = __shfl_xor_sync(0xffffffffu, m2[q], d);
            int   bi2 = __shfl_xor_sync(0xffffffffu, i2[q], d);
            float bm3 = __shfl_xor_sync(0xffffffffu, m3[q], d);
            merge3(m1[q], i1[q], m2[q], i2[q], m3[q], bm1, bi1, bm2, bi2, bm3);
        }
    }

    // finalize: each warp owns its rows (no cross-warp merge)
    if ((lane & 3) == 0) {
#pragma unroll
        for (int q = 0; q < 4; q++) {
            int r = wid * 32 + (q >> 1) * 16 + (q & 1) * 8 + (lane >> 2);
            int n   = ntb * TM + r;
            int row = h * N_ + n;
            g_idx[row] = i1[q];
            if (!(m2[q] - m1[q] > W_SEL)) {
                if (m3[q] - m1[q] > W_SEL) {
                    // winner provably in {i1, i2}: exact reference-order compare
                    int c1 = i1[q], c2 = i2[q];
                    const float* xp  = x  + (size_t)n * DIM_ + h * DK_;
                    const float* kp1 = ke + ((size_t)h * C_ + c1) * DK_;
                    const float* kp2 = ke + ((size_t)h * C_ + c2) * DK_;
                    float x2 = 0.f, d1 = 0.f, d2 = 0.f;
#pragma unroll
                    for (int d = 0; d < DK_; d++) {
                        float xv = __ldg(xp + d);
                        x2 = __fmaf_rn(xv, xv, x2);
                        d1 = __fmaf_rn(xv, __ldg(kp1 + d), d1);
                        d2 = __fmaf_rn(xv, __ldg(kp2 + d), d2);
                    }
                    float s1 = __fadd_rn(__fmaf_rn(-2.f, d1, x2), e2h[c1]);
                    float s2 = __fadd_rn(__fmaf_rn(-2.f, d2, x2), e2h[c2]);
                    g_idx[row] = (s2 < s1 || (s2 == s1 && c2 < c1)) ? c2 : c1;
                } else {
                    int p = atomicAdd(&g_cntB, 1);
                    g_listB[p] = row;
                }
            }
        }
    }
}

// ---------------------------------------------------------------------------
// Full replay (rare rows): exact fp32, smem-staged coalesced
// ---------------------------------------------------------------------------
__global__ void replay_kernel(const float* __restrict__ x,
                              const float* __restrict__ ke) {
    __shared__ float kt[128 * 65];
    __shared__ float xsr[DK_];
    __shared__ float rv[128];
    __shared__ int   ri[128];
    const int tid = threadIdx.x;
    for (int e = blockIdx.x; e < g_cntB; e += gridDim.x) {
        int row = g_listB[e];
        int h = row >> 12, n = row & (N_ - 1);
        if (tid < DK_) xsr[tid] = x[(size_t)n * DIM_ + h * DK_ + tid];
        __syncthreads();
        float x2 = 0.f;
#pragma unroll
        for (int d = 0; d < DK_; d++) x2 = __fmaf_rn(xsr[d], xsr[d], x2);
        const float* keh = ke + (size_t)h * C_ * DK_;
        const float* e2h = g_e2 + h * C_;
        float bv = CUDART_INF_F; int bi = 0;
        for (int tile = 0; tile < C_ / 128; tile++) {
            const float* kb = keh + (size_t)tile * 128 * DK_;
#pragma unroll 4
            for (int m = tid; m < 128 * 16; m += 128) {
                int r = m >> 4, c4 = m & 15;
                float4 v = *(const float4*)(kb + (size_t)r * DK_ + c4 * 4);
                kt[r * 65 + c4 * 4 + 0] = v.x;
                kt[r * 65 + c4 * 4 + 1] = v.y;
                kt[r * 65 + c4 * 4 + 2] = v.z;
                kt[r * 65 + c4 * 4 + 3] = v.w;
            }
            __syncthreads();
            float dot = 0.f;
#pragma unroll
            for (int d = 0; d < DK_; d++) dot = __fmaf_rn(xsr[d], kt[tid * 65 + d], dot);
            float s = __fadd_rn(__fmaf_rn(-2.f, dot, x2), e2h[tile * 128 + tid]);
            int c = tile * 128 + tid;
            if (s < bv) { bv = s; bi = c; }
            __syncthreads();
        }
        rv[tid] = bv; ri[tid] = bi;
        __syncthreads();
        if (tid == 0) {
            float b = rv[0]; int bix = ri[0];
            for (int t = 1; t < 128; t++) {
                float v = rv[t]; int c = ri[t];
                if (v < b || (v == b && c < bix)) { b = v; bix = c; }
            }
            g_idx[row] = bix;
        }
        __syncthreads();
    }
}

// ---------------------------------------------------------------------------
// Gather
// ---------------------------------------------------------------------------
__global__ void gather_kernel(const float* __restrict__ vals,
                              float* __restrict__ out) {
    int lin = blockIdx.x * blockDim.x + threadIdx.x;
    if (lin >= H_ * N_ * 16) return;
    int v4 = lin & 15; int hn = lin >> 4;
    int n = hn & (N_ - 1); int h = hn >> 12;
    int c = g_idx[hn];
    float4 v = *(const float4*)(vals + ((size_t)h * C_ + c) * DV_ + v4 * 4);
    *(float4*)(out + (size_t)n * DIM_ + h * DV_ + v4 * 4) = v;
}

// ---------------------------------------------------------------------------
extern "C" void kernel_launch(void* const* d_in, const int* in_sizes, int n_in,
                              void* d_out, int out_size) {
    const float* x    = (const float*)d_in[0];
    const float* ke   = (const float*)d_in[2];
    const float* vals = (const float*)d_in[3];
    float* out = (float*)d_out;

    cudaFuncSetAttribute(hmma_argmin_kernel,
                         cudaFuncAttributeMaxDynamicSharedMemorySize, SMEM_SZ);

    prep_be2_kernel<<<H_ * C_ / 64, 256>>>(ke);

    dim3 grid(N_ / TM, H_);
    hmma_argmin_kernel<<<grid, 128, SMEM_SZ>>>(x, ke);

    replay_kernel<<<148, 128>>>(x, ke);
    gather_kernel<<<(H_ * N_ * 16) / 256, 256>>>(vals, out);
}

// round 16
// speedup vs baseline: 1.0152x; 1.0152x over previous
#include <cuda_runtime.h>
#include <cuda_fp16.h>
#include <math_constants.h>
#include <stdint.h>

// Problem dims
#define B_   4
#define T_   1024
#define H_   12
#define C_   4096
#define DK_  64
#define DV_  64
#define N_   (B_*T_)      // 4096
#define DIM_ (H_*DK_)     // 768

// GEMM config: single-phase fp16 (K=64), certification window handles error.
#define TM   128          // rows per CTA
#define TCC  64           // codes per iteration
#define NCT  (C_/TCC)     // 64
#define SA   144          // A smem row stride bytes (128 data + 16 pad)
#define PACK_BYTES 8448   // per-tile record: 64 codes x 128B (swizzled) + 64 e2 floats
#define W_SEL 5e-4f       // ambiguity window (~20 sigma of fp16-GEMM error)

// smem offsets
#define OFF_A   0                  // 128 * 144 = 18432
#define OFF_B   18432              // 3 buffers of 8448 = 25344 (128-aligned)
#define OFF_MB  43776              // 3 mbarriers (8B each)
#define SMEM_SZ 43808

// Device scratch
__device__ __align__(1024) unsigned char g_pack[(size_t)H_*NCT*PACK_BYTES];
__device__ float g_e2[H_*C_];
__device__ int   g_idx[H_*N_];
__device__ int   g_listB[H_*N_];
__device__ int   g_cntB;

// ---------------- helpers ----------------
__device__ __forceinline__ uint32_t smem_u32(const void* p) {
    uint32_t a;
    asm("{ .reg .u64 t; cvta.to.shared.u64 t, %1; cvt.u32.u64 %0, t; }" : "=r"(a) : "l"(p));
    return a;
}
__device__ __forceinline__ void mbar_init(uint32_t mb, uint32_t cnt) {
    asm volatile("mbarrier.init.shared.b64 [%0], %1;" :: "r"(mb), "r"(cnt) : "memory");
}
__device__ __forceinline__ void mbar_expect_tx(uint32_t mb, uint32_t bytes) {
    asm volatile("mbarrier.arrive.expect_tx.shared.b64 _, [%0], %1;"
                 :: "r"(mb), "r"(bytes) : "memory");
}
__device__ __forceinline__ void bulk_g2s(uint32_t dst, const void* src,
                                         uint32_t bytes, uint32_t mb) {
    asm volatile("cp.async.bulk.shared::cluster.global.mbarrier::complete_tx::bytes "
                 "[%0], [%1], %2, [%3];"
                 :: "r"(dst), "l"(src), "r"(bytes), "r"(mb) : "memory");
}
__device__ __forceinline__ void mbar_wait(uint32_t mb, uint32_t parity) {
    asm volatile("{\n\t.reg .pred P;\n\tMWL%=:\n\t"
                 "mbarrier.try_wait.parity.acquire.cta.shared::cta.b64 P, [%0], %1, 0x989680;\n\t"
                 "@P bra.uni MWD%=;\n\tbra.uni MWL%=;\n\tMWD%=:\n\t}"
                 :: "r"(mb), "r"(parity) : "memory");
}

__device__ __forceinline__ void ldsm4(uint32_t* r, uint32_t addr) {
    asm volatile("ldmatrix.sync.aligned.m8n8.x4.shared.b16 {%0,%1,%2,%3}, [%4];"
                 : "=r"(r[0]), "=r"(r[1]), "=r"(r[2]), "=r"(r[3]) : "r"(addr));
}
__device__ __forceinline__ void mma16816(float* d, const uint32_t* a, const uint32_t* b) {
    asm volatile("mma.sync.aligned.m16n8k16.row.col.f32.f16.f16.f32 "
                 "{%0,%1,%2,%3}, {%4,%5,%6,%7}, {%8,%9}, {%0,%1,%2,%3};"
                 : "+f"(d[0]), "+f"(d[1]), "+f"(d[2]), "+f"(d[3])
                 : "r"(a[0]), "r"(a[1]), "r"(a[2]), "r"(a[3]), "r"(b[0]), "r"(b[1]));
}

__device__ __forceinline__ void merge3(float& m1, int& i1, float& m2, int& i2, float& m3,
                                       float bm1, int bi1, float bm2, int bi2, float bm3) {
    if (bm1 < m1 || (bm1 == m1 && bi1 < i1)) {
        float t; int ti;
        t = m1; m1 = bm1; bm1 = t;  ti = i1; i1 = bi1; bi1 = ti;
        t = m2; m2 = bm2; bm2 = t;  ti = i2; i2 = bi2; bi2 = ti;
        t = m3; m3 = bm3; bm3 = t;
    }
    if (bm1 < m2 || (bm1 == m2 && bi1 < i2)) {
        m3 = fminf(m2, bm2);
        m2 = bm1; i2 = bi1;
    } else {
        m3 = fminf(m3, bm1);
    }
}

__device__ __forceinline__ void ins3(float s, int c, float& m1, int& i1,
                                     float& m2, int& i2, float& m3) {
    if (s < m1)      { m3 = m2; m2 = m1; i2 = i1; m1 = s; i1 = c; }
    else if (s < m2) { m3 = m2; m2 = s; i2 = c; }
    else if (s < m3) { m3 = s; }
}

// ---------------------------------------------------------------------------
// Fused prep: e2 (exact sequential order) + packed swizzled fp16 B records.
// grid = H*NCT = 768 blocks of 256; block g covers codes [g*64, g*64+64).
// Record layout: [64 rows x 128B, byte b of row r at r*128 + (b ^ ((r&7)<<4))]
//                [offset 8192: 64 x float e2]
// ---------------------------------------------------------------------------
__global__ void prep_be2_kernel(const float* __restrict__ ke) {
    __shared__ float kt[64 * 65];
    const int tid = threadIdx.x;
    const int row0 = blockIdx.x * 64;          // global code row (h*C + c)
    unsigned char* pk = g_pack + (size_t)blockIdx.x * PACK_BYTES;
    if (blockIdx.x == 0 && tid == 0) g_cntB = 0;

#pragma unroll 4
    for (int m = tid; m < 64 * 16; m += 256) {
        int r = m >> 4, c4 = m & 15;
        float4 v = *(const float4*)(ke + (size_t)(row0 + r) * DK_ + c4 * 4);
        kt[r * 65 + c4 * 4 + 0] = v.x;
        kt[r * 65 + c4 * 4 + 1] = v.y;
        kt[r * 65 + c4 * 4 + 2] = v.z;
        kt[r * 65 + c4 * 4 + 3] = v.w;
    }
    __syncthreads();

    if (tid < 64) {
        float s = 0.f;
#pragma unroll
        for (int d = 0; d < DK_; d++) {
            float v = kt[tid * 65 + d];
            s = __fmaf_rn(v, v, s);
        }
        g_e2[row0 + tid] = s;
        *(float*)(pk + 8192 + tid * 4) = s;
    }

    // fp16 convert + swizzle into the packed record
#pragma unroll 4
    for (int m = tid; m < 64 * 32; m += 256) {
        int r = m >> 5, dp = m & 31;
        __half2 hv = __floats2half2_rn(kt[r * 65 + dp * 2], kt[r * 65 + dp * 2 + 1]);
        uint32_t boff = (uint32_t)(dp * 4) ^ (uint32_t)((r & 7) << 4);
        *(__half2*)(pk + r * 128 + boff) = hv;
    }
}

// ---------------------------------------------------------------------------
// Main: fp16 HMMA GEMM (K=64) + top-3 argmin; persistent A frags;
// B tiles via single cp.async.bulk per iteration (mbarrier completion),
// triple-buffered distance-2.
// grid = (32, 12); block = 128 (4 warps, each 32 rows x 64 cols)
// ---------------------------------------------------------------------------
__global__ __launch_bounds__(128, 3)
void hmma_argmin_kernel(const float* __restrict__ x,
                        const float* __restrict__ ke) {
    extern __shared__ char smem[];
    const uint32_t sb = smem_u32(smem);
    const int tid = threadIdx.x, lane = tid & 31, wid = tid >> 5;
    const int h = blockIdx.y, ntb = blockIdx.x;

    const unsigned char* Pg = g_pack + (size_t)(h * NCT) * PACK_BYTES;
    const float* e2h = g_e2 + h * C_;

    // mbarriers (one per buffer), count=1 (producer's arrive.expect_tx)
    if (tid == 0) {
        mbar_init(sb + OFF_MB + 0, 1);
        mbar_init(sb + OFF_MB + 8, 1);
        mbar_init(sb + OFF_MB + 16, 1);
    }
    __syncthreads();

    // Prologue: issue bulk copies for tiles 0 and 1
    if (tid == 0) {
        mbar_expect_tx(sb + OFF_MB + 0, PACK_BYTES);
        bulk_g2s(sb + OFF_B, Pg, PACK_BYTES, sb + OFF_MB + 0);
        mbar_expect_tx(sb + OFF_MB + 8, PACK_BYTES);
        bulk_g2s(sb + OFF_B + PACK_BYTES, Pg + PACK_BYTES, PACK_BYTES, sb + OFF_MB + 8);
    }

    // A tile converted in-kernel to fp16: 128 rows x 128 B (stride SA)
    {
        const float* xb = x + (size_t)(ntb * TM) * DIM_ + h * DK_;
#pragma unroll 8
        for (int m = tid; m < TM * 32; m += 128) {
            int r = m >> 5, dp = m & 31;
            float2 v = *(const float2*)(xb + (size_t)r * DIM_ + dp * 2);
            __half2 hv = __floats2half2_rn(v.x, v.y);
            *(__half2*)(smem + OFF_A + r * SA + dp * 4) = hv;
        }
    }
    __syncthreads();   // A tile visible

    // A ldmatrix base + persistent fragments
    const uint32_t aAddr = sb + OFF_A +
        (uint32_t)((wid * 32 + (lane & 15)) * SA + (lane >> 4) * 16);
    uint32_t afr[4][2][4];
#pragma unroll
    for (int ks = 0; ks < 4; ks++)
#pragma unroll
        for (int mt = 0; mt < 2; mt++)
            ldsm4(afr[ks][mt], aAddr + mt * (16 * SA) + ks * 32);

    // B addressing in swizzled-linear layout (128B rows):
    // row for np-tile = (lane&7) + ((lane>>4)&1)*8 + np*16
    // byte-in-row = (ks*32 + ((lane>>3)&1)*16) ^ ((lane&7)<<4)
    const uint32_t xr = (uint32_t)((lane & 7) << 4);
    const uint32_t hi16 = (uint32_t)(((lane >> 3) & 1) * 16);
    uint32_t brow[4];
#pragma unroll
    for (int np = 0; np < 4; np++)
        brow[np] = (uint32_t)(((lane & 7) + ((lane >> 4) & 1) * 8 + np * 16) * 128);

    float m1[4], m2[4], m3[4]; int i1[4], i2[4];
#pragma unroll
    for (int q = 0; q < 4; q++) {
        m1[q] = CUDART_INF_F; m2[q] = CUDART_INF_F; m3[q] = CUDART_INF_F;
        i1[q] = 0; i2[q] = 0;
    }

    int bc = 0;                        // buffer of tile ct (= ct % 3)
    for (int ct = 0; ct < NCT; ct++) {
        // wait tile ct complete; parity = (use index)&1 = (ct/3)&1
        mbar_wait(sb + OFF_MB + bc * 8, (uint32_t)((ct / 3) & 1));
        __syncthreads();               // all warps finished reading tile ct-1

        // issue bulk for tile ct+2 into buffer (bc+2)%3
        if (ct + 2 < NCT && tid == 0) {
            int bp = bc + 2; if (bp >= 3) bp -= 3;
            mbar_expect_tx(sb + OFF_MB + bp * 8, PACK_BYTES);
            bulk_g2s(sb + OFF_B + bp * PACK_BYTES,
                     Pg + (size_t)(ct + 2) * PACK_BYTES,
                     PACK_BYTES, sb + OFF_MB + bp * 8);
        }

        float acc[2][8][4];
#pragma unroll
        for (int mt = 0; mt < 2; mt++)
#pragma unroll
            for (int nt = 0; nt < 8; nt++)
#pragma unroll
                for (int v = 0; v < 4; v++) acc[mt][nt][v] = 0.f;

        const uint32_t bbase = sb + OFF_B + bc * PACK_BYTES;

#pragma unroll
        for (int ks = 0; ks < 4; ks++) {
            const uint32_t col = ((uint32_t)(ks * 32) + hi16) ^ xr;
            uint32_t b[4][4];
#pragma unroll
            for (int np = 0; np < 4; np++)
                ldsm4(b[np], bbase + brow[np] + col);
#pragma unroll
            for (int mt = 0; mt < 2; mt++)
#pragma unroll
                for (int nt = 0; nt < 8; nt++)
                    mma16816(acc[mt][nt], afr[ks][mt], &b[nt >> 1][(nt & 1) * 2]);
        }

        // epilogue: s = e2 - 2*dot; paired fminf fast path vs m3
        const float* e2c = (const float*)(smem + OFF_B + bc * PACK_BYTES + 8192)
                           + (lane & 3) * 2;
        const int cth = ct * TCC + (lane & 3) * 2;
#pragma unroll
        for (int nt = 0; nt < 8; nt++) {
            float e20 = e2c[nt * 8], e21 = e2c[nt * 8 + 1];
#pragma unroll
            for (int mt = 0; mt < 2; mt++) {
#pragma unroll
                for (int vp = 0; vp < 2; vp++) {
                    float s0 = fmaf(-2.f, acc[mt][nt][vp * 2],     e20);
                    float s1 = fmaf(-2.f, acc[mt][nt][vp * 2 + 1], e21);
                    int q = mt * 2 + vp;
                    if (fminf(s0, s1) < m3[q]) {        // rare after warmup
                        int c = cth + nt * 8;
                        ins3(s0, c,     m1[q], i1[q], m2[q], i2[q], m3[q]);
                        ins3(s1, c + 1, m1[q], i1[q], m2[q], i2[q], m3[q]);
                    }
                }
            }
        }
        bc = bc + 1; if (bc >= 3) bc = 0;
    }

    // quad reduce (lanes xor 1,2 cover disjoint columns, same rows)
#pragma unroll
    for (int q = 0; q < 4; q++) {
#pragma unroll
        for (int d = 1; d <= 2; d <<= 1) {
            float bm1 = __shfl_xor_sync(0xffffffffu, m1[q], d);
            int   bi1 = __shfl_xor_sync(0xffffffffu, i1[q], d);
            float bm2 = __shfl_xor_sync(0xffffffffu, m2[q], d);
            int   bi2 = __shfl_xor_sync(0xffffffffu, i2[q], d);
            float bm3 = __shfl_xor_sync(0xffffffffu, m3[q], d);
            merge3(m1[q], i1[q], m2[q], i2[q], m3[q], bm1, bi1, bm2, bi2, bm3);
        }
    }

    // finalize: each warp owns its rows (no cross-warp merge)
    if ((lane & 3) == 0) {
#pragma unroll
        for (int q = 0; q < 4; q++) {
            int r = wid * 32 + (q >> 1) * 16 + (q & 1) * 8 + (lane >> 2);
            int n   = ntb * TM + r;
            int row = h * N_ + n;
            g_idx[row] = i1[q];
            if (!(m2[q] - m1[q] > W_SEL)) {
                if (m3[q] - m1[q] > W_SEL) {
                    // winner provably in {i1, i2}: exact reference-order compare
                    int c1 = i1[q], c2 = i2[q];
                    const float* xp  = x  + (size_t)n * DIM_ + h * DK_;
                    const float* kp1 = ke + ((size_t)h * C_ + c1) * DK_;
                    const float* kp2 = ke + ((size_t)h * C_ + c2) * DK_;
                    float x2 = 0.f, d1 = 0.f, d2 = 0.f;
#pragma unroll
                    for (int d = 0; d < DK_; d++) {
                        float xv = __ldg(xp + d);
                        x2 = __fmaf_rn(xv, xv, x2);
                        d1 = __fmaf_rn(xv, __ldg(kp1 + d), d1);
                        d2 = __fmaf_rn(xv, __ldg(kp2 + d), d2);
                    }
                    float s1 = __fadd_rn(__fmaf_rn(-2.f, d1, x2), e2h[c1]);
                    float s2 = __fadd_rn(__fmaf_rn(-2.f, d2, x2), e2h[c2]);
                    g_idx[row] = (s2 < s1 || (s2 == s1 && c2 < c1)) ? c2 : c1;
                } else {
                    int p = atomicAdd(&g_cntB, 1);
                    g_listB[p] = row;
                }
            }
        }
    }
}

// ---------------------------------------------------------------------------
// Full replay (rare rows): exact fp32, smem-staged coalesced
// ---------------------------------------------------------------------------
__global__ void replay_kernel(const float* __restrict__ x,
                              const float* __restrict__ ke) {
    __shared__ float kt[128 * 65];
    __shared__ float xsr[DK_];
    __shared__ float rv[128];
    __shared__ int   ri[128];
    const int tid = threadIdx.x;
    for (int e = blockIdx.x; e < g_cntB; e += gridDim.x) {
        int row = g_listB[e];
        int h = row >> 12, n = row & (N_ - 1);
        if (tid < DK_) xsr[tid] = x[(size_t)n * DIM_ + h * DK_ + tid];
        __syncthreads();
        float x2 = 0.f;
#pragma unroll
        for (int d = 0; d < DK_; d++) x2 = __fmaf_rn(xsr[d], xsr[d], x2);
        const float* keh = ke + (size_t)h * C_ * DK_;
        const float* e2h = g_e2 + h * C_;
        float bv = CUDART_INF_F; int bi = 0;
        for (int tile = 0; tile < C_ / 128; tile++) {
            const float* kb = keh + (size_t)tile * 128 * DK_;
#pragma unroll 4
            for (int m = tid; m < 128 * 16; m += 128) {
                int r = m >> 4, c4 = m & 15;
                float4 v = *(const float4*)(kb + (size_t)r * DK_ + c4 * 4);
                kt[r * 65 + c4 * 4 + 0] = v.x;
                kt[r * 65 + c4 * 4 + 1] = v.y;
                kt[r * 65 + c4 * 4 + 2] = v.z;
                kt[r * 65 + c4 * 4 + 3] = v.w;
            }
            __syncthreads();
            float dot = 0.f;
#pragma unroll
            for (int d = 0; d < DK_; d++) dot = __fmaf_rn(xsr[d], kt[tid * 65 + d], dot);
            float s = __fadd_rn(__fmaf_rn(-2.f, dot, x2), e2h[tile * 128 + tid]);
            int c = tile * 128 + tid;
            if (s < bv) { bv = s; bi = c; }
            __syncthreads();
        }
        rv[tid] = bv; ri[tid] = bi;
        __syncthreads();
        if (tid == 0) {
            float b = rv[0]; int bix = ri[0];
            for (int t = 1; t < 128; t++) {
                float v = rv[t]; int c = ri[t];
                if (v < b || (v == b && c < bix)) { b = v; bix = c; }
            }
            g_idx[row] = bix;
        }
        __syncthreads();
    }
}

// ---------------------------------------------------------------------------
// Gather
// ---------------------------------------------------------------------------
__global__ void gather_kernel(const float* __restrict__ vals,
                              float* __restrict__ out) {
    int lin = blockIdx.x * blockDim.x + threadIdx.x;
    if (lin >= H_ * N_ * 16) return;
    int v4 = lin & 15; int hn = lin >> 4;
    int n = hn & (N_ - 1); int h = hn >> 12;
    int c = g_idx[hn];
    float4 v = *(const float4*)(vals + ((size_t)h * C_ + c) * DV_ + v4 * 4);
    *(float4*)(out + (size_t)n * DIM_ + h * DV_ + v4 * 4) = v;
}

// ---------------------------------------------------------------------------
extern "C" void kernel_launch(void* const* d_in, const int* in_sizes, int n_in,
                              void* d_out, int out_size) {
    const float* x    = (const float*)d_in[0];
    const float* ke   = (const float*)d_in[2];
    const float* vals = (const float*)d_in[3];
    float* out = (float*)d_out;

    cudaFuncSetAttribute(hmma_argmin_kernel,
                         cudaFuncAttributeMaxDynamicSharedMemorySize, SMEM_SZ);

    prep_be2_kernel<<<H_ * NCT, 256>>>(ke);

    dim3 grid(N_ / TM, H_);
    hmma_argmin_kernel<<<grid, 128, SMEM_SZ>>>(x, ke);

    replay_kernel<<<148, 128>>>(x, ke);
    gather_kernel<<<(H_ * N_ * 16) / 256, 256>>>(vals, out);
}

// round 17
// speedup vs baseline: 1.0167x; 1.0015x over previous
#include <cuda_runtime.h>
#include <cuda_fp16.h>
#include <math_constants.h>
#include <stdint.h>

// Problem dims
#define B_   4
#define T_   1024
#define H_   12
#define C_   4096
#define DK_  64
#define DV_  64
#define N_   (B_*T_)      // 4096
#define DIM_ (H_*DK_)     // 768

// GEMM config: single-phase fp16 (K=64), certification window handles error.
#define TM   128          // rows per CTA
#define TCC  64           // codes per iteration
#define NCT  (C_/TCC)     // 64
#define SA   144          // A smem row stride bytes (128 data + 16 pad)
#define PACK_BYTES 8448   // per-tile record: 64 codes x 128B (swizzled) + 64 e2 floats
#define W_SEL 5e-4f       // ambiguity window (~20 sigma of fp16-GEMM error)

// smem offsets
#define OFF_A    0                  // 128 * 144 = 18432
#define OFF_B    18432              // 3 buffers of 8448 = 25344
#define OFF_MBF  43776              // 3 "full" mbarriers (8B each)
#define OFF_MBC  43800              // 3 "consumed" mbarriers (8B each)
#define SMEM_SZ  43840

// Device scratch
__device__ __align__(1024) unsigned char g_pack[(size_t)H_*NCT*PACK_BYTES];
__device__ float g_e2[H_*C_];
__device__ int   g_idx[H_*N_];
__device__ int   g_listB[H_*N_];
__device__ int   g_cntB;

// ---------------- helpers ----------------
__device__ __forceinline__ uint32_t smem_u32(const void* p) {
    uint32_t a;
    asm("{ .reg .u64 t; cvta.to.shared.u64 t, %1; cvt.u32.u64 %0, t; }" : "=r"(a) : "l"(p));
    return a;
}
__device__ __forceinline__ void mbar_init(uint32_t mb, uint32_t cnt) {
    asm volatile("mbarrier.init.shared.b64 [%0], %1;" :: "r"(mb), "r"(cnt) : "memory");
}
__device__ __forceinline__ void mbar_expect_tx(uint32_t mb, uint32_t bytes) {
    asm volatile("mbarrier.arrive.expect_tx.shared.b64 _, [%0], %1;"
                 :: "r"(mb), "r"(bytes) : "memory");
}
__device__ __forceinline__ void mbar_arrive(uint32_t mb) {
    asm volatile("mbarrier.arrive.shared.b64 _, [%0];" :: "r"(mb) : "memory");
}
__device__ __forceinline__ void bulk_g2s(uint32_t dst, const void* src,
                                         uint32_t bytes, uint32_t mb) {
    asm volatile("cp.async.bulk.shared::cluster.global.mbarrier::complete_tx::bytes "
                 "[%0], [%1], %2, [%3];"
                 :: "r"(dst), "l"(src), "r"(bytes), "r"(mb) : "memory");
}
__device__ __forceinline__ void mbar_wait(uint32_t mb, uint32_t parity) {
    asm volatile("{\n\t.reg .pred P;\n\tMWL%=:\n\t"
                 "mbarrier.try_wait.parity.acquire.cta.shared::cta.b64 P, [%0], %1, 0x989680;\n\t"
                 "@P bra.uni MWD%=;\n\tbra.uni MWL%=;\n\tMWD%=:\n\t}"
                 :: "r"(mb), "r"(parity) : "memory");
}

__device__ __forceinline__ void ldsm4(uint32_t* r, uint32_t addr) {
    asm volatile("ldmatrix.sync.aligned.m8n8.x4.shared.b16 {%0,%1,%2,%3}, [%4];"
                 : "=r"(r[0]), "=r"(r[1]), "=r"(r[2]), "=r"(r[3]) : "r"(addr));
}
__device__ __forceinline__ void mma16816(float* d, const uint32_t* a, const uint32_t* b) {
    asm volatile("mma.sync.aligned.m16n8k16.row.col.f32.f16.f16.f32 "
                 "{%0,%1,%2,%3}, {%4,%5,%6,%7}, {%8,%9}, {%0,%1,%2,%3};"
                 : "+f"(d[0]), "+f"(d[1]), "+f"(d[2]), "+f"(d[3])
                 : "r"(a[0]), "r"(a[1]), "r"(a[2]), "r"(a[3]), "r"(b[0]), "r"(b[1]));
}
// first k-step: D = A*B + 0 (kills explicit acc zeroing)
__device__ __forceinline__ void mma16816_z(float* d, const uint32_t* a, const uint32_t* b,
                                           float z) {
    asm volatile("mma.sync.aligned.m16n8k16.row.col.f32.f16.f16.f32 "
                 "{%0,%1,%2,%3}, {%4,%5,%6,%7}, {%8,%9}, {%10,%10,%10,%10};"
                 : "=f"(d[0]), "=f"(d[1]), "=f"(d[2]), "=f"(d[3])
                 : "r"(a[0]), "r"(a[1]), "r"(a[2]), "r"(a[3]), "r"(b[0]), "r"(b[1]),
                   "f"(z));
}

__device__ __forceinline__ void merge3(float& m1, int& i1, float& m2, int& i2, float& m3,
                                       float bm1, int bi1, float bm2, int bi2, float bm3) {
    if (bm1 < m1 || (bm1 == m1 && bi1 < i1)) {
        float t; int ti;
        t = m1; m1 = bm1; bm1 = t;  ti = i1; i1 = bi1; bi1 = ti;
        t = m2; m2 = bm2; bm2 = t;  ti = i2; i2 = bi2; bi2 = ti;
        t = m3; m3 = bm3; bm3 = t;
    }
    if (bm1 < m2 || (bm1 == m2 && bi1 < i2)) {
        m3 = fminf(m2, bm2);
        m2 = bm1; i2 = bi1;
    } else {
        m3 = fminf(m3, bm1);
    }
}

__device__ __forceinline__ void ins3(float s, int c, float& m1, int& i1,
                                     float& m2, int& i2, float& m3) {
    if (s < m1)      { m3 = m2; m2 = m1; i2 = i1; m1 = s; i1 = c; }
    else if (s < m2) { m3 = m2; m2 = s; i2 = c; }
    else if (s < m3) { m3 = s; }
}

// ---------------------------------------------------------------------------
// Fused prep: e2 (exact sequential order) + packed swizzled fp16 B records.
// ---------------------------------------------------------------------------
__global__ void prep_be2_kernel(const float* __restrict__ ke) {
    __shared__ float kt[64 * 65];
    const int tid = threadIdx.x;
    const int row0 = blockIdx.x * 64;
    unsigned char* pk = g_pack + (size_t)blockIdx.x * PACK_BYTES;
    if (blockIdx.x == 0 && tid == 0) g_cntB = 0;

#pragma unroll 4
    for (int m = tid; m < 64 * 16; m += 256) {
        int r = m >> 4, c4 = m & 15;
        float4 v = *(const float4*)(ke + (size_t)(row0 + r) * DK_ + c4 * 4);
        kt[r * 65 + c4 * 4 + 0] = v.x;
        kt[r * 65 + c4 * 4 + 1] = v.y;
        kt[r * 65 + c4 * 4 + 2] = v.z;
        kt[r * 65 + c4 * 4 + 3] = v.w;
    }
    __syncthreads();

    if (tid < 64) {
        float s = 0.f;
#pragma unroll
        for (int d = 0; d < DK_; d++) {
            float v = kt[tid * 65 + d];
            s = __fmaf_rn(v, v, s);
        }
        g_e2[row0 + tid] = s;
        *(float*)(pk + 8192 + tid * 4) = s;
    }

#pragma unroll 4
    for (int m = tid; m < 64 * 32; m += 256) {
        int r = m >> 5, dp = m & 31;
        __half2 hv = __floats2half2_rn(kt[r * 65 + dp * 2], kt[r * 65 + dp * 2 + 1]);
        uint32_t boff = (uint32_t)(dp * 4) ^ (uint32_t)((r & 7) << 4);
        *(__half2*)(pk + r * 128 + boff) = hv;
    }
}

// ---------------------------------------------------------------------------
// Main: fp16 HMMA GEMM (K=64) + top-3 argmin; free-running warps:
// per-buffer full/consumed mbarriers, NO per-iteration __syncthreads.
// grid = (32, 12); block = 128 (4 warps, each 32 rows x 64 cols)
// ---------------------------------------------------------------------------
__global__ __launch_bounds__(128, 3)
void hmma_argmin_kernel(const float* __restrict__ x,
                        const float* __restrict__ ke) {
    extern __shared__ char smem[];
    const uint32_t sb = smem_u32(smem);
    const int tid = threadIdx.x, lane = tid & 31, wid = tid >> 5;
    const int h = blockIdx.y, ntb = blockIdx.x;

    const unsigned char* Pg = g_pack + (size_t)(h * NCT) * PACK_BYTES;
    const float* e2h = g_e2 + h * C_;

    // mbarriers: full[b] count=1 (producer expect_tx); consumed[b] count=4
    if (tid == 0) {
#pragma unroll
        for (int b = 0; b < 3; b++) {
            mbar_init(sb + OFF_MBF + b * 8, 1);
            mbar_init(sb + OFF_MBC + b * 8, 4);
        }
    }
    __syncthreads();

    // Prologue: issue bulk copies for tiles 0 and 1
    if (tid == 0) {
        mbar_expect_tx(sb + OFF_MBF + 0, PACK_BYTES);
        bulk_g2s(sb + OFF_B, Pg, PACK_BYTES, sb + OFF_MBF + 0);
        mbar_expect_tx(sb + OFF_MBF + 8, PACK_BYTES);
        bulk_g2s(sb + OFF_B + PACK_BYTES, Pg + PACK_BYTES, PACK_BYTES, sb + OFF_MBF + 8);
    }

    // A tile converted in-kernel to fp16: 128 rows x 128 B (stride SA)
    {
        const float* xb = x + (size_t)(ntb * TM) * DIM_ + h * DK_;
#pragma unroll 8
        for (int m = tid; m < TM * 32; m += 128) {
            int r = m >> 5, dp = m & 31;
            float2 v = *(const float2*)(xb + (size_t)r * DIM_ + dp * 2);
            __half2 hv = __floats2half2_rn(v.x, v.y);
            *(__half2*)(smem + OFF_A + r * SA + dp * 4) = hv;
        }
    }
    __syncthreads();   // A tile visible (last CTA-wide barrier before finalize)

    // A ldmatrix base + persistent fragments
    const uint32_t aAddr = sb + OFF_A +
        (uint32_t)((wid * 32 + (lane & 15)) * SA + (lane >> 4) * 16);
    uint32_t afr[4][2][4];
#pragma unroll
    for (int ks = 0; ks < 4; ks++)
#pragma unroll
        for (int mt = 0; mt < 2; mt++)
            ldsm4(afr[ks][mt], aAddr + mt * (16 * SA) + ks * 32);

    // B addressing in swizzled-linear layout (128B rows)
    const uint32_t xr = (uint32_t)((lane & 7) << 4);
    const uint32_t hi16 = (uint32_t)(((lane >> 3) & 1) * 16);
    uint32_t brow[4];
#pragma unroll
    for (int np = 0; np < 4; np++)
        brow[np] = (uint32_t)(((lane & 7) + ((lane >> 4) & 1) * 8 + np * 16) * 128);

    float m1[4], m2[4], m3[4]; int i1[4], i2[4];
#pragma unroll
    for (int q = 0; q < 4; q++) {
        m1[q] = CUDART_INF_F; m2[q] = CUDART_INF_F; m3[q] = CUDART_INF_F;
        i1[q] = 0; i2[q] = 0;
    }
    const float zero = 0.f;

    int bc = 0;                        // buffer of tile ct (= ct % 3)
    for (int ct = 0; ct < NCT; ct++) {
        // Producer: issue tile ct+2 into buffer (ct+2)%3.
        // Must first wait until tile ct-1 (same buffer) is consumed by all warps.
        if (tid == 0 && ct + 2 < NCT) {
            int bp = bc + 2; if (bp >= 3) bp -= 3;
            if (ct >= 1)   // buffer previously used by tile ct-1, consumed-phase (ct-1)/3
                mbar_wait(sb + OFF_MBC + bp * 8, (uint32_t)(((ct - 1) / 3) & 1));
            mbar_expect_tx(sb + OFF_MBF + bp * 8, PACK_BYTES);
            bulk_g2s(sb + OFF_B + bp * PACK_BYTES,
                     Pg + (size_t)(ct + 2) * PACK_BYTES,
                     PACK_BYTES, sb + OFF_MBF + bp * 8);
        }

        // Consumer (per warp, free-running): wait tile ct data
        mbar_wait(sb + OFF_MBF + bc * 8, (uint32_t)((ct / 3) & 1));

        const uint32_t bbase = sb + OFF_B + bc * PACK_BYTES;
        float acc[2][8][4];

#pragma unroll
        for (int ks = 0; ks < 4; ks++) {
            const uint32_t col = ((uint32_t)(ks * 32) + hi16) ^ xr;
            uint32_t b[4][4];
#pragma unroll
            for (int np = 0; np < 4; np++)
                ldsm4(b[np], bbase + brow[np] + col);
            if (ks == 0) {
#pragma unroll
                for (int mt = 0; mt < 2; mt++)
#pragma unroll
                    for (int nt = 0; nt < 8; nt++)
                        mma16816_z(acc[mt][nt], afr[0][mt], &b[nt >> 1][(nt & 1) * 2], zero);
            } else {
#pragma unroll
                for (int mt = 0; mt < 2; mt++)
#pragma unroll
                    for (int nt = 0; nt < 8; nt++)
                        mma16816(acc[mt][nt], afr[ks][mt], &b[nt >> 1][(nt & 1) * 2]);
            }
        }

        // epilogue: s = e2 - 2*dot; paired fminf fast path vs m3
        const float* e2c = (const float*)(smem + OFF_B + bc * PACK_BYTES + 8192)
                           + (lane & 3) * 2;
        const int cth = ct * TCC + (lane & 3) * 2;
#pragma unroll
        for (int nt = 0; nt < 8; nt++) {
            float e20 = e2c[nt * 8], e21 = e2c[nt * 8 + 1];
#pragma unroll
            for (int mt = 0; mt < 2; mt++) {
#pragma unroll
                for (int vp = 0; vp < 2; vp++) {
                    float s0 = fmaf(-2.f, acc[mt][nt][vp * 2],     e20);
                    float s1 = fmaf(-2.f, acc[mt][nt][vp * 2 + 1], e21);
                    int q = mt * 2 + vp;
                    if (fminf(s0, s1) < m3[q]) {        // rare after warmup
                        int c = cth + nt * 8;
                        ins3(s0, c,     m1[q], i1[q], m2[q], i2[q], m3[q]);
                        ins3(s1, c + 1, m1[q], i1[q], m2[q], i2[q], m3[q]);
                    }
                }
            }
        }

        // this warp is done with buffer bc (all smem reads data-consumed above)
        if (lane == 0) mbar_arrive(sb + OFF_MBC + bc * 8);
        bc = bc + 1; if (bc >= 3) bc = 0;
    }

    // quad reduce (lanes xor 1,2 cover disjoint columns, same rows)
#pragma unroll
    for (int q = 0; q < 4; q++) {
#pragma unroll
        for (int d = 1; d <= 2; d <<= 1) {
            float bm1 = __shfl_xor_sync(0xffffffffu, m1[q], d);
            int   bi1 = __shfl_xor_sync(0xffffffffu, i1[q], d);
            float bm2 = __shfl_xor_sync(0xffffffffu, m2[q], d);
            int   bi2 = __shfl_xor_sync(0xffffffffu, i2[q], d);
            float bm3 = __shfl_xor_sync(0xffffffffu, m3[q], d);
            merge3(m1[q], i1[q], m2[q], i2[q], m3[q], bm1, bi1, bm2, bi2, bm3);
        }
    }

    // finalize: each warp owns its rows (no cross-warp merge)
    if ((lane & 3) == 0) {
#pragma unroll
        for (int q = 0; q < 4; q++) {
            int r = wid * 32 + (q >> 1) * 16 + (q & 1) * 8 + (lane >> 2);
            int n   = ntb * TM + r;
            int row = h * N_ + n;
            g_idx[row] = i1[q];
            if (!(m2[q] - m1[q] > W_SEL)) {
                if (m3[q] - m1[q] > W_SEL) {
                    // winner provably in {i1, i2}: exact reference-order compare
                    int c1 = i1[q], c2 = i2[q];
                    const float* xp  = x  + (size_t)n * DIM_ + h * DK_;
                    const float* kp1 = ke + ((size_t)h * C_ + c1) * DK_;
                    const float* kp2 = ke + ((size_t)h * C_ + c2) * DK_;
                    float x2 = 0.f, d1 = 0.f, d2 = 0.f;
#pragma unroll
                    for (int d = 0; d < DK_; d++) {
                        float xv = __ldg(xp + d);
                        x2 = __fmaf_rn(xv, xv, x2);
                        d1 = __fmaf_rn(xv, __ldg(kp1 + d), d1);
                        d2 = __fmaf_rn(xv, __ldg(kp2 + d), d2);
                    }
                    float s1 = __fadd_rn(__fmaf_rn(-2.f, d1, x2), e2h[c1]);
                    float s2 = __fadd_rn(__fmaf_rn(-2.f, d2, x2), e2h[c2]);
                    g_idx[row] = (s2 < s1 || (s2 == s1 && c2 < c1)) ? c2 : c1;
                } else {
                    int p = atomicAdd(&g_cntB, 1);
                    g_listB[p] = row;
                }
            }
        }
    }
}

// ---------------------------------------------------------------------------
// Full replay (rare rows): exact fp32, smem-staged coalesced
// ---------------------------------------------------------------------------
__global__ void replay_kernel(const float* __restrict__ x,
                              const float* __restrict__ ke) {
    __shared__ float kt[128 * 65];
    __shared__ float xsr[DK_];
    __shared__ float rv[128];
    __shared__ int   ri[128];
    const int tid = threadIdx.x;
    for (int e = blockIdx.x; e < g_cntB; e += gridDim.x) {
        int row = g_listB[e];
        int h = row >> 12, n = row & (N_ - 1);
        if (tid < DK_) xsr[tid] = x[(size_t)n * DIM_ + h * DK_ + tid];
        __syncthreads();
        float x2 = 0.f;
#pragma unroll
        for (int d = 0; d < DK_; d++) x2 = __fmaf_rn(xsr[d], xsr[d], x2);
        const float* keh = ke + (size_t)h * C_ * DK_;
        const float* e2h = g_e2 + h * C_;
        float bv = CUDART_INF_F; int bi = 0;
        for (int tile = 0; tile < C_ / 128; tile++) {
            const float* kb = keh + (size_t)tile * 128 * DK_;
#pragma unroll 4
            for (int m = tid; m < 128 * 16; m += 128) {
                int r = m >> 4, c4 = m & 15;
                float4 v = *(const float4*)(kb + (size_t)r * DK_ + c4 * 4);
                kt[r * 65 + c4 * 4 + 0] = v.x;
                kt[r * 65 + c4 * 4 + 1] = v.y;
                kt[r * 65 + c4 * 4 + 2] = v.z;
                kt[r * 65 + c4 * 4 + 3] = v.w;
            }
            __syncthreads();
            float dot = 0.f;
#pragma unroll
            for (int d = 0; d < DK_; d++) dot = __fmaf_rn(xsr[d], kt[tid * 65 + d], dot);
            float s = __fadd_rn(__fmaf_rn(-2.f, dot, x2), e2h[tile * 128 + tid]);
            int c = tile * 128 + tid;
            if (s < bv) { bv = s; bi = c; }
            __syncthreads();
        }
        rv[tid] = bv; ri[tid] = bi;
        __syncthreads();
        if (tid == 0) {
            float b = rv[0]; int bix = ri[0];
            for (int t = 1; t < 128; t++) {
                float v = rv[t]; int c = ri[t];
                if (v < b || (v == b && c < bix)) { b = v; bix = c; }
            }
            g_idx[row] = bix;
        }
        __syncthreads();
    }
}

// ---------------------------------------------------------------------------
// Gather
// ---------------------------------------------------------------------------
__global__ void gather_kernel(const float* __restrict__ vals,
                              float* __restrict__ out) {
    int lin = blockIdx.x * blockDim.x + threadIdx.x;
    if (lin >= H_ * N_ * 16) return;
    int v4 = lin & 15; int hn = lin >> 4;
    int n = hn & (N_ - 1); int h = hn >> 12;
    int c = g_idx[hn];
    float4 v = *(const float4*)(vals + ((size_t)h * C_ + c) * DV_ + v4 * 4);
    *(float4*)(out + (size_t)n * DIM_ + h * DV_ + v4 * 4) = v;
}

// ---------------------------------------------------------------------------
extern "C" void kernel_launch(void* const* d_in, const int* in_sizes, int n_in,
                              void* d_out, int out_size) {
    const float* x    = (const float*)d_in[0];
    const float* ke   = (const float*)d_in[2];
    const float* vals = (const float*)d_in[3];
    float* out = (float*)d_out;

    cudaFuncSetAttribute(hmma_argmin_kernel,
                         cudaFuncAttributeMaxDynamicSharedMemorySize, SMEM_SZ);

    prep_be2_kernel<<<H_ * NCT, 256>>>(ke);

    dim3 grid(N_ / TM, H_);
    hmma_argmin_kernel<<<grid, 128, SMEM_SZ>>>(x, ke);

    replay_kernel<<<148, 128>>>(x, ke);
    gather_kernel<<<(H_ * N_ * 16) / 256, 256>>>(vals, out);
}